// round 6
// baseline (speedup 1.0000x reference)
#include <cuda_runtime.h>
#include <cstdint>

#define NN 50000
#define DD 128
#define EDIM 16
#define NE 800000
#define NB 49   // ceil(NN/1024)

// packed fp32x2 helpers (Blackwell FFMA2 path)
#define PACK2(d, lo, hi)  asm("mov.b64 %0, {%1, %2};" : "=l"(d) : "f"(lo), "f"(hi))
#define UNPACK2(lo, hi, s) asm("mov.b64 {%0, %1}, %2;" : "=f"(lo), "=f"(hi) : "l"(s))
#define FMA2(d, a, b, c)  asm("fma.rn.f32x2 %0, %1, %2, %3;" : "=l"(d) : "l"(a), "l"(b), "l"(c))
#define ADD2(d, a, b)     asm("add.rn.f32x2 %0, %1, %2;" : "=l"(d) : "l"(a), "l"(b))

// ---------------- device scratch ----------------
__device__ float g_Wef[EDIM * DD];
__device__ float g_bef[DD];
__device__ float g_W1[DD * 256];
__device__ float g_b1[256];
__device__ float g_W2[256 * DD];
__device__ float g_b2[DD];
__device__ float g_acc[(size_t)NN * DD];
__device__ float g_t[(size_t)NN * 256];
__device__ int   g_count[NN];
__device__ int   g_cursor[NN];
__device__ int   g_csum[NN];
__device__ int   g_bsum[64];
__device__ int2  g_epack[NE];

// ---------------- prep ----------------
__global__ void prep_kernel(const float* __restrict__ We1, const float* __restrict__ be1,
                            const float* __restrict__ We2, const float* __restrict__ be2,
                            const float* __restrict__ Wm1, const float* __restrict__ bm1,
                            const float* __restrict__ g1, const float* __restrict__ b1,
                            const float* __restrict__ m1, const float* __restrict__ v1,
                            const float* __restrict__ Wm2, const float* __restrict__ bm2,
                            const float* __restrict__ g2, const float* __restrict__ b2,
                            const float* __restrict__ m2, const float* __restrict__ v2) {
    int i = blockIdx.x * blockDim.x + threadIdx.x;

    if (i < NN) { g_count[i] = 0; g_cursor[i] = 0; }

    if (i < EDIM * DD) {
        int k = i / DD, d = i % DD;
        float s = 0.f;
        for (int j = 0; j < 256; j++) s += We1[k * 256 + j] * We2[j * DD + d];
        g_Wef[i] = s;
    }
    if (i < DD) {
        float s = be2[i];
        for (int j = 0; j < 256; j++) s += be1[j] * We2[j * DD + i];
        g_bef[i] = s;
    }
    if (i < DD * 256) {
        int j = i % 256;
        float a = g1[j] * rsqrtf(v1[j] + 1e-3f);
        g_W1[i] = Wm1[i] * a;
    }
    if (i < 256) {
        float a = g1[i] * rsqrtf(v1[i] + 1e-3f);
        g_b1[i] = bm1[i] * a + b1[i] - m1[i] * a;
    }
    if (i < 256 * DD) {
        int j = i % DD;
        float a = g2[j] * rsqrtf(v2[j] + 1e-3f);
        g_W2[i] = Wm2[i] * a;
    }
    if (i < DD) {
        float a = g2[i] * rsqrtf(v2[i] + 1e-3f);
        g_b2[i] = bm2[i] * a + b2[i] - m2[i] * a;
    }
}

// ---------------- CSR build ----------------
__global__ void hist_kernel(const int* __restrict__ dst) {
    int i = blockIdx.x * blockDim.x + threadIdx.x;
    if (i < NE) atomicAdd(&g_count[dst[i]], 1);
}

__global__ void scan1_kernel() {
    __shared__ int sm[1024];
    int i = blockIdx.x * 1024 + threadIdx.x;
    int v = (i < NN) ? g_count[i] : 0;
    sm[threadIdx.x] = v;
    __syncthreads();
    for (int off = 1; off < 1024; off <<= 1) {
        int add = (threadIdx.x >= off) ? sm[threadIdx.x - off] : 0;
        __syncthreads();
        sm[threadIdx.x] += add;
        __syncthreads();
    }
    if (i < NN) g_csum[i] = sm[threadIdx.x];
    if (threadIdx.x == 1023) g_bsum[blockIdx.x] = sm[1023];
}

__global__ void scan3_kernel() {
    __shared__ int off;
    if (threadIdx.x == 0) {
        int s = 0;
        for (int j = 0; j < (int)blockIdx.x; j++) s += g_bsum[j];
        off = s;
    }
    __syncthreads();
    int i = blockIdx.x * 1024 + threadIdx.x;
    if (i < NN) g_csum[i] += off;
}

__global__ void scatter_kernel(const int* __restrict__ src, const int* __restrict__ dst) {
    int i = blockIdx.x * blockDim.x + threadIdx.x;
    if (i < NE) {
        int t = dst[i];
        int beg = g_csum[t] - g_count[t];
        int pos = beg + atomicAdd(&g_cursor[t], 1);
        g_epack[pos] = make_int2(i, src[i]);
    }
}

// ---------------- per-node accumulation ----------------
// TWO warps per node: thread tx in [0,64) owns channels 2*tx, 2*tx+1.
// Weights in registers (16 x u64 = 32 regs), no smem in the loop.
__global__ void __launch_bounds__(256) accum_kernel(const float* __restrict__ node,
                                                    const float* __restrict__ efeat,
                                                    const float* __restrict__ eps) {
    const int tx = threadIdx.x;                 // 0..63
    uint64_t w2[EDIM];
#pragma unroll
    for (int k = 0; k < EDIM; k++) {
        float2 wv = *reinterpret_cast<const float2*>(g_Wef + k * DD + tx * 2);
        PACK2(w2[k], wv.x, wv.y);
    }
    float2 bias = *reinterpret_cast<const float2*>(g_bef + tx * 2);
    uint64_t bias2;
    PACK2(bias2, bias.x, bias.y);

    const int n = blockIdx.x * blockDim.y + threadIdx.y;
    if (n >= NN) return;

    const float se = 1.f + eps[0];
    float2 acc = *reinterpret_cast<const float2*>(node + (size_t)n * DD + tx * 2);
    acc.x *= se; acc.y *= se;

    const int end = g_csum[n];
    const int beg = end - g_count[n];
    int2 es = (beg < end) ? g_epack[beg] : make_int2(0, 0);
    for (int p = beg; p < end; p++) {
        int2 cur = es;
        if (p + 1 < end) es = g_epack[p + 1];   // prefetch next entry (linear addr)
        float2 nf = *reinterpret_cast<const float2*>(node + (size_t)cur.y * DD + tx * 2);
        const float4* ep = reinterpret_cast<const float4*>(efeat + (size_t)cur.x * EDIM);
        float4 f0 = ep[0], f1 = ep[1], f2 = ep[2], f3 = ep[3];   // warp broadcast
        float ef[EDIM] = {f0.x, f0.y, f0.z, f0.w, f1.x, f1.y, f1.z, f1.w,
                          f2.x, f2.y, f2.z, f2.w, f3.x, f3.y, f3.z, f3.w};
        uint64_t v0, n0;
        PACK2(n0, nf.x, nf.y);
        ADD2(v0, bias2, n0);
#pragma unroll
        for (int k = 0; k < EDIM; k++) {
            uint64_t e2;
            PACK2(e2, ef[k], ef[k]);
            FMA2(v0, e2, w2[k], v0);
        }
        float x, y;
        UNPACK2(x, y, v0);
        acc.x += fmaxf(x, 0.f);
        acc.y += fmaxf(y, 0.f);
    }
    *reinterpret_cast<float2*>(g_acc + (size_t)n * DD + tx * 2) = acc;
}

// ---------------- tiled fp32 GEMM with packed fp32x2 FMAs ----------------
__global__ void __launch_bounds__(256) gemm_kernel(const float* __restrict__ A,
                                                   const float* __restrict__ B,
                                                   const float* __restrict__ bias,
                                                   float* __restrict__ C,
                                                   int M, int N, int K, int relu) {
    __shared__ float As[8][128];
    __shared__ float Bs[8][128];

    const int tid = threadIdx.x;
    const int tx = tid % 16;
    const int ty = tid / 16;
    const int m0 = blockIdx.x * 128;
    const int n0 = blockIdx.y * 128;

    const int ar = tid >> 1;
    const int ac = (tid & 1) * 4;
    const int br = tid >> 5;
    const int bc = (tid & 31) * 4;

    uint64_t acc2[8][4];
#pragma unroll
    for (int i = 0; i < 8; i++)
#pragma unroll
        for (int j = 0; j < 4; j++) acc2[i][j] = 0ull;

    for (int k0 = 0; k0 < K; k0 += 8) {
        float4 av = make_float4(0.f, 0.f, 0.f, 0.f);
        if (m0 + ar < M)
            av = *reinterpret_cast<const float4*>(A + (size_t)(m0 + ar) * K + k0 + ac);
        As[ac + 0][ar] = av.x;
        As[ac + 1][ar] = av.y;
        As[ac + 2][ar] = av.z;
        As[ac + 3][ar] = av.w;
        float4 bv = *reinterpret_cast<const float4*>(B + (size_t)(k0 + br) * N + n0 + bc);
        *reinterpret_cast<float4*>(&Bs[br][bc]) = bv;
        __syncthreads();

#pragma unroll
        for (int kk = 0; kk < 8; kk++) {
            float4 a0 = *reinterpret_cast<const float4*>(&As[kk][ty * 8]);
            float4 a1 = *reinterpret_cast<const float4*>(&As[kk][ty * 8 + 4]);
            float4 b0 = *reinterpret_cast<const float4*>(&Bs[kk][tx * 8]);
            float4 b1 = *reinterpret_cast<const float4*>(&Bs[kk][tx * 8 + 4]);
            uint64_t b2[4];
            PACK2(b2[0], b0.x, b0.y);
            PACK2(b2[1], b0.z, b0.w);
            PACK2(b2[2], b1.x, b1.y);
            PACK2(b2[3], b1.z, b1.w);
            float a8[8] = {a0.x, a0.y, a0.z, a0.w, a1.x, a1.y, a1.z, a1.w};
#pragma unroll
            for (int i = 0; i < 8; i++) {
                uint64_t a2;
                PACK2(a2, a8[i], a8[i]);
#pragma unroll
                for (int j = 0; j < 4; j++)
                    FMA2(acc2[i][j], a2, b2[j], acc2[i][j]);
            }
        }
        __syncthreads();
    }

    float bj[8];
#pragma unroll
    for (int j = 0; j < 8; j++) bj[j] = bias[n0 + tx * 8 + j];

#pragma unroll
    for (int i = 0; i < 8; i++) {
        int row = m0 + ty * 8 + i;
        if (row < M) {
            float out[8];
#pragma unroll
            for (int j = 0; j < 4; j++) {
                float lo, hi;
                UNPACK2(lo, hi, acc2[i][j]);
                float v0 = lo + bj[2 * j];
                float v1 = hi + bj[2 * j + 1];
                out[2 * j]     = relu ? fmaxf(v0, 0.f) : v0;
                out[2 * j + 1] = relu ? fmaxf(v1, 0.f) : v1;
            }
            float4* cp = reinterpret_cast<float4*>(C + (size_t)row * N + n0 + tx * 8);
            cp[0] = make_float4(out[0], out[1], out[2], out[3]);
            cp[1] = make_float4(out[4], out[5], out[6], out[7]);
        }
    }
}

// ---------------- launch ----------------
extern "C" void kernel_launch(void* const* d_in, const int* in_sizes, int n_in,
                              void* d_out, int out_size) {
    const float* node  = (const float*)d_in[0];
    const float* efeat = (const float*)d_in[1];
    const int*   src   = (const int*)d_in[2];
    const int*   dst   = (const int*)d_in[3];
    const float* We1 = (const float*)d_in[4];
    const float* be1 = (const float*)d_in[5];
    const float* We2 = (const float*)d_in[6];
    const float* be2 = (const float*)d_in[7];
    const float* eps = (const float*)d_in[8];
    const float* Wm1 = (const float*)d_in[9];
    const float* bm1 = (const float*)d_in[10];
    const float* g1  = (const float*)d_in[11];
    const float* b1  = (const float*)d_in[12];
    const float* m1  = (const float*)d_in[13];
    const float* v1  = (const float*)d_in[14];
    const float* Wm2 = (const float*)d_in[15];
    const float* bm2 = (const float*)d_in[16];
    const float* g2  = (const float*)d_in[17];
    const float* b2  = (const float*)d_in[18];
    const float* m2  = (const float*)d_in[19];
    const float* v2  = (const float*)d_in[20];
    float* out = (float*)d_out;

    prep_kernel<<<256, 256>>>(We1, be1, We2, be2, Wm1, bm1, g1, b1, m1, v1,
                              Wm2, bm2, g2, b2, m2, v2);

    hist_kernel<<<(NE + 255) / 256, 256>>>(dst);
    scan1_kernel<<<NB, 1024>>>();
    scan3_kernel<<<NB, 1024>>>();
    scatter_kernel<<<(NE + 255) / 256, 256>>>(src, dst);

    // 2 warps per node, 4 nodes per block
    accum_kernel<<<(NN + 3) / 4, dim3(64, 4)>>>(node, efeat, eps);

    float *pacc, *pt, *pW1, *pb1, *pW2, *pb2;
    cudaGetSymbolAddress((void**)&pacc, g_acc);
    cudaGetSymbolAddress((void**)&pt,   g_t);
    cudaGetSymbolAddress((void**)&pW1,  g_W1);
    cudaGetSymbolAddress((void**)&pb1,  g_b1);
    cudaGetSymbolAddress((void**)&pW2,  g_W2);
    cudaGetSymbolAddress((void**)&pb2,  g_b2);

    gemm_kernel<<<dim3((NN + 127) / 128, 256 / 128), 256>>>(pacc, pW1, pb1, pt,
                                                            NN, 256, DD, 1);
    gemm_kernel<<<dim3((NN + 127) / 128, DD / 128), 256>>>(pt, pW2, pb2, out,
                                                           NN, DD, 256, 0);
}

// round 7
// speedup vs baseline: 1.4051x; 1.4051x over previous
#include <cuda_runtime.h>
#include <cstdint>

#define NN 50000
#define DD 128
#define EDIM 16
#define NE 800000
#define NB 49   // ceil(NN/1024)

// packed fp32x2 helpers (Blackwell FFMA2 path)
#define PACK2(d, lo, hi)  asm("mov.b64 %0, {%1, %2};" : "=l"(d) : "f"(lo), "f"(hi))
#define UNPACK2(lo, hi, s) asm("mov.b64 {%0, %1}, %2;" : "=f"(lo), "=f"(hi) : "l"(s))
#define FMA2(d, a, b, c)  asm("fma.rn.f32x2 %0, %1, %2, %3;" : "=l"(d) : "l"(a), "l"(b), "l"(c))
#define ADD2(d, a, b)     asm("add.rn.f32x2 %0, %1, %2;" : "=l"(d) : "l"(a), "l"(b))

// ---------------- device scratch ----------------
__device__ float g_Wef[EDIM * DD];
__device__ float g_bef[DD];
__device__ float g_W1[DD * 256];
__device__ float g_b1[256];
__device__ float g_W2[256 * DD];
__device__ float g_b2[DD];
__device__ float g_acc[(size_t)NN * DD];
__device__ float g_t[(size_t)NN * 256];
__device__ int   g_count[NN];
__device__ int   g_cursor[NN];
__device__ int   g_csum[NN];
__device__ int   g_bsum[64];
__device__ int2  g_epack[NE];

// ---------------- prep ----------------
__global__ void prep_kernel(const float* __restrict__ We1, const float* __restrict__ be1,
                            const float* __restrict__ We2, const float* __restrict__ be2,
                            const float* __restrict__ Wm1, const float* __restrict__ bm1,
                            const float* __restrict__ g1, const float* __restrict__ b1,
                            const float* __restrict__ m1, const float* __restrict__ v1,
                            const float* __restrict__ Wm2, const float* __restrict__ bm2,
                            const float* __restrict__ g2, const float* __restrict__ b2,
                            const float* __restrict__ m2, const float* __restrict__ v2) {
    int i = blockIdx.x * blockDim.x + threadIdx.x;

    if (i < NN) { g_count[i] = 0; g_cursor[i] = 0; }

    if (i < EDIM * DD) {
        int k = i / DD, d = i % DD;
        float s = 0.f;
        for (int j = 0; j < 256; j++) s += We1[k * 256 + j] * We2[j * DD + d];
        g_Wef[i] = s;
    }
    if (i < DD) {
        float s = be2[i];
        for (int j = 0; j < 256; j++) s += be1[j] * We2[j * DD + i];
        g_bef[i] = s;
    }
    if (i < DD * 256) {
        int j = i % 256;
        float a = g1[j] * rsqrtf(v1[j] + 1e-3f);
        g_W1[i] = Wm1[i] * a;
    }
    if (i < 256) {
        float a = g1[i] * rsqrtf(v1[i] + 1e-3f);
        g_b1[i] = bm1[i] * a + b1[i] - m1[i] * a;
    }
    if (i < 256 * DD) {
        int j = i % DD;
        float a = g2[j] * rsqrtf(v2[j] + 1e-3f);
        g_W2[i] = Wm2[i] * a;
    }
    if (i < DD) {
        float a = g2[i] * rsqrtf(v2[i] + 1e-3f);
        g_b2[i] = bm2[i] * a + b2[i] - m2[i] * a;
    }
}

// ---------------- CSR build ----------------
__global__ void hist_kernel(const int* __restrict__ dst) {
    int i = blockIdx.x * blockDim.x + threadIdx.x;
    if (i < NE) atomicAdd(&g_count[dst[i]], 1);
}

__global__ void scan1_kernel() {
    __shared__ int sm[1024];
    int i = blockIdx.x * 1024 + threadIdx.x;
    int v = (i < NN) ? g_count[i] : 0;
    sm[threadIdx.x] = v;
    __syncthreads();
    for (int off = 1; off < 1024; off <<= 1) {
        int add = (threadIdx.x >= off) ? sm[threadIdx.x - off] : 0;
        __syncthreads();
        sm[threadIdx.x] += add;
        __syncthreads();
    }
    if (i < NN) g_csum[i] = sm[threadIdx.x];
    if (threadIdx.x == 1023) g_bsum[blockIdx.x] = sm[1023];
}

__global__ void scan3_kernel() {
    __shared__ int off;
    if (threadIdx.x == 0) {
        int s = 0;
        for (int j = 0; j < (int)blockIdx.x; j++) s += g_bsum[j];
        off = s;
    }
    __syncthreads();
    int i = blockIdx.x * 1024 + threadIdx.x;
    if (i < NN) g_csum[i] += off;
}

__global__ void scatter_kernel(const int* __restrict__ src, const int* __restrict__ dst) {
    int i = blockIdx.x * blockDim.x + threadIdx.x;
    if (i < NE) {
        int t = dst[i];
        int beg = g_csum[t] - g_count[t];
        int pos = beg + atomicAdd(&g_cursor[t], 1);
        g_epack[pos] = make_int2(i, src[i]);
    }
}

// ---------------- per-node accumulation ----------------
// One warp per node, lane owns channels 4*lane..4*lane+3 (R4 layout).
// 128-thread blocks for 3 blocks/SM occupancy; 2-edge ILP unroll so two
// independent node-row gathers are in flight per warp.
__global__ void __launch_bounds__(128) accum_kernel(const float* __restrict__ node,
                                                    const float* __restrict__ efeat,
                                                    const float* __restrict__ eps) {
    const int lane = threadIdx.x;
    uint64_t w2[EDIM][2];
#pragma unroll
    for (int k = 0; k < EDIM; k++) {
        float4 wv = *reinterpret_cast<const float4*>(g_Wef + k * DD + lane * 4);
        PACK2(w2[k][0], wv.x, wv.y);
        PACK2(w2[k][1], wv.z, wv.w);
    }
    float4 bias = *reinterpret_cast<const float4*>(g_bef + lane * 4);
    uint64_t bias2[2];
    PACK2(bias2[0], bias.x, bias.y);
    PACK2(bias2[1], bias.z, bias.w);

    const int n = blockIdx.x * blockDim.y + threadIdx.y;
    if (n >= NN) return;

    const float se = 1.f + eps[0];
    float4 acc = *reinterpret_cast<const float4*>(node + (size_t)n * DD + lane * 4);
    acc.x *= se; acc.y *= se; acc.z *= se; acc.w *= se;

    const int end = g_csum[n];
    const int beg = end - g_count[n];

    int2 e0 = make_int2(0, 0), e1 = make_int2(0, 0);
    if (beg < end)     e0 = g_epack[beg];
    if (beg + 1 < end) e1 = g_epack[beg + 1];

    int p = beg;
    for (; p + 1 < end; p += 2) {
        int2 ca = e0, cb = e1;
        if (p + 2 < end) e0 = g_epack[p + 2];
        if (p + 3 < end) e1 = g_epack[p + 3];

        // issue both gathers before consuming either
        float4 nfa = *reinterpret_cast<const float4*>(node + (size_t)ca.y * DD + lane * 4);
        float4 nfb = *reinterpret_cast<const float4*>(node + (size_t)cb.y * DD + lane * 4);
        const float4* epa = reinterpret_cast<const float4*>(efeat + (size_t)ca.x * EDIM);
        const float4* epb = reinterpret_cast<const float4*>(efeat + (size_t)cb.x * EDIM);
        float4 a0 = epa[0], a1 = epa[1], a2v = epa[2], a3 = epa[3];
        float4 b0 = epb[0], b1 = epb[1], b2v = epb[2], b3 = epb[3];

        float efa[EDIM] = {a0.x, a0.y, a0.z, a0.w, a1.x, a1.y, a1.z, a1.w,
                           a2v.x, a2v.y, a2v.z, a2v.w, a3.x, a3.y, a3.z, a3.w};
        float efb[EDIM] = {b0.x, b0.y, b0.z, b0.w, b1.x, b1.y, b1.z, b1.w,
                           b2v.x, b2v.y, b2v.z, b2v.w, b3.x, b3.y, b3.z, b3.w};

        uint64_t va0, va1, vb0, vb1, t0, t1;
        PACK2(t0, nfa.x, nfa.y);
        PACK2(t1, nfa.z, nfa.w);
        ADD2(va0, bias2[0], t0);
        ADD2(va1, bias2[1], t1);
        PACK2(t0, nfb.x, nfb.y);
        PACK2(t1, nfb.z, nfb.w);
        ADD2(vb0, bias2[0], t0);
        ADD2(vb1, bias2[1], t1);
#pragma unroll
        for (int k = 0; k < EDIM; k++) {
            uint64_t ea, eb;
            PACK2(ea, efa[k], efa[k]);
            PACK2(eb, efb[k], efb[k]);
            FMA2(va0, ea, w2[k][0], va0);
            FMA2(va1, ea, w2[k][1], va1);
            FMA2(vb0, eb, w2[k][0], vb0);
            FMA2(vb1, eb, w2[k][1], vb1);
        }
        float x, y, z, w;
        UNPACK2(x, y, va0);
        UNPACK2(z, w, va1);
        acc.x += fmaxf(x, 0.f);
        acc.y += fmaxf(y, 0.f);
        acc.z += fmaxf(z, 0.f);
        acc.w += fmaxf(w, 0.f);
        UNPACK2(x, y, vb0);
        UNPACK2(z, w, vb1);
        acc.x += fmaxf(x, 0.f);
        acc.y += fmaxf(y, 0.f);
        acc.z += fmaxf(z, 0.f);
        acc.w += fmaxf(w, 0.f);
    }
    if (p < end) {
        int2 cur = e0;
        float4 nf = *reinterpret_cast<const float4*>(node + (size_t)cur.y * DD + lane * 4);
        const float4* ep = reinterpret_cast<const float4*>(efeat + (size_t)cur.x * EDIM);
        float4 f0 = ep[0], f1 = ep[1], f2 = ep[2], f3 = ep[3];
        float ef[EDIM] = {f0.x, f0.y, f0.z, f0.w, f1.x, f1.y, f1.z, f1.w,
                          f2.x, f2.y, f2.z, f2.w, f3.x, f3.y, f3.z, f3.w};
        uint64_t v0, v1, n0, n1;
        PACK2(n0, nf.x, nf.y);
        PACK2(n1, nf.z, nf.w);
        ADD2(v0, bias2[0], n0);
        ADD2(v1, bias2[1], n1);
#pragma unroll
        for (int k = 0; k < EDIM; k++) {
            uint64_t e2;
            PACK2(e2, ef[k], ef[k]);
            FMA2(v0, e2, w2[k][0], v0);
            FMA2(v1, e2, w2[k][1], v1);
        }
        float x, y, z, w;
        UNPACK2(x, y, v0);
        UNPACK2(z, w, v1);
        acc.x += fmaxf(x, 0.f);
        acc.y += fmaxf(y, 0.f);
        acc.z += fmaxf(z, 0.f);
        acc.w += fmaxf(w, 0.f);
    }
    *reinterpret_cast<float4*>(g_acc + (size_t)n * DD + lane * 4) = acc;
}

// ---------------- tiled fp32 GEMM with packed fp32x2 FMAs ----------------
__global__ void __launch_bounds__(256) gemm_kernel(const float* __restrict__ A,
                                                   const float* __restrict__ B,
                                                   const float* __restrict__ bias,
                                                   float* __restrict__ C,
                                                   int M, int N, int K, int relu) {
    __shared__ float As[8][128];
    __shared__ float Bs[8][128];

    const int tid = threadIdx.x;
    const int tx = tid % 16;
    const int ty = tid / 16;
    const int m0 = blockIdx.x * 128;
    const int n0 = blockIdx.y * 128;

    const int ar = tid >> 1;
    const int ac = (tid & 1) * 4;
    const int br = tid >> 5;
    const int bc = (tid & 31) * 4;

    uint64_t acc2[8][4];
#pragma unroll
    for (int i = 0; i < 8; i++)
#pragma unroll
        for (int j = 0; j < 4; j++) acc2[i][j] = 0ull;

    for (int k0 = 0; k0 < K; k0 += 8) {
        float4 av = make_float4(0.f, 0.f, 0.f, 0.f);
        if (m0 + ar < M)
            av = *reinterpret_cast<const float4*>(A + (size_t)(m0 + ar) * K + k0 + ac);
        As[ac + 0][ar] = av.x;
        As[ac + 1][ar] = av.y;
        As[ac + 2][ar] = av.z;
        As[ac + 3][ar] = av.w;
        float4 bv = *reinterpret_cast<const float4*>(B + (size_t)(k0 + br) * N + n0 + bc);
        *reinterpret_cast<float4*>(&Bs[br][bc]) = bv;
        __syncthreads();

#pragma unroll
        for (int kk = 0; kk < 8; kk++) {
            float4 a0 = *reinterpret_cast<const float4*>(&As[kk][ty * 8]);
            float4 a1 = *reinterpret_cast<const float4*>(&As[kk][ty * 8 + 4]);
            float4 b0 = *reinterpret_cast<const float4*>(&Bs[kk][tx * 8]);
            float4 b1 = *reinterpret_cast<const float4*>(&Bs[kk][tx * 8 + 4]);
            uint64_t b2[4];
            PACK2(b2[0], b0.x, b0.y);
            PACK2(b2[1], b0.z, b0.w);
            PACK2(b2[2], b1.x, b1.y);
            PACK2(b2[3], b1.z, b1.w);
            float a8[8] = {a0.x, a0.y, a0.z, a0.w, a1.x, a1.y, a1.z, a1.w};
#pragma unroll
            for (int i = 0; i < 8; i++) {
                uint64_t a2;
                PACK2(a2, a8[i], a8[i]);
#pragma unroll
                for (int j = 0; j < 4; j++)
                    FMA2(acc2[i][j], a2, b2[j], acc2[i][j]);
            }
        }
        __syncthreads();
    }

    float bj[8];
#pragma unroll
    for (int j = 0; j < 8; j++) bj[j] = bias[n0 + tx * 8 + j];

#pragma unroll
    for (int i = 0; i < 8; i++) {
        int row = m0 + ty * 8 + i;
        if (row < M) {
            float out[8];
#pragma unroll
            for (int j = 0; j < 4; j++) {
                float lo, hi;
                UNPACK2(lo, hi, acc2[i][j]);
                float v0 = lo + bj[2 * j];
                float v1 = hi + bj[2 * j + 1];
                out[2 * j]     = relu ? fmaxf(v0, 0.f) : v0;
                out[2 * j + 1] = relu ? fmaxf(v1, 0.f) : v1;
            }
            float4* cp = reinterpret_cast<float4*>(C + (size_t)row * N + n0 + tx * 8);
            cp[0] = make_float4(out[0], out[1], out[2], out[3]);
            cp[1] = make_float4(out[4], out[5], out[6], out[7]);
        }
    }
}

// ---------------- launch ----------------
extern "C" void kernel_launch(void* const* d_in, const int* in_sizes, int n_in,
                              void* d_out, int out_size) {
    const float* node  = (const float*)d_in[0];
    const float* efeat = (const float*)d_in[1];
    const int*   src   = (const int*)d_in[2];
    const int*   dst   = (const int*)d_in[3];
    const float* We1 = (const float*)d_in[4];
    const float* be1 = (const float*)d_in[5];
    const float* We2 = (const float*)d_in[6];
    const float* be2 = (const float*)d_in[7];
    const float* eps = (const float*)d_in[8];
    const float* Wm1 = (const float*)d_in[9];
    const float* bm1 = (const float*)d_in[10];
    const float* g1  = (const float*)d_in[11];
    const float* b1  = (const float*)d_in[12];
    const float* m1  = (const float*)d_in[13];
    const float* v1  = (const float*)d_in[14];
    const float* Wm2 = (const float*)d_in[15];
    const float* bm2 = (const float*)d_in[16];
    const float* g2  = (const float*)d_in[17];
    const float* b2  = (const float*)d_in[18];
    const float* m2  = (const float*)d_in[19];
    const float* v2  = (const float*)d_in[20];
    float* out = (float*)d_out;

    prep_kernel<<<256, 256>>>(We1, be1, We2, be2, Wm1, bm1, g1, b1, m1, v1,
                              Wm2, bm2, g2, b2, m2, v2);

    hist_kernel<<<(NE + 255) / 256, 256>>>(dst);
    scan1_kernel<<<NB, 1024>>>();
    scan3_kernel<<<NB, 1024>>>();
    scatter_kernel<<<(NE + 255) / 256, 256>>>(src, dst);

    // 1 warp per node, 4 nodes per 128-thread block (3 blocks/SM occupancy)
    accum_kernel<<<(NN + 3) / 4, dim3(32, 4)>>>(node, efeat, eps);

    float *pacc, *pt, *pW1, *pb1, *pW2, *pb2;
    cudaGetSymbolAddress((void**)&pacc, g_acc);
    cudaGetSymbolAddress((void**)&pt,   g_t);
    cudaGetSymbolAddress((void**)&pW1,  g_W1);
    cudaGetSymbolAddress((void**)&pb1,  g_b1);
    cudaGetSymbolAddress((void**)&pW2,  g_W2);
    cudaGetSymbolAddress((void**)&pb2,  g_b2);

    gemm_kernel<<<dim3((NN + 127) / 128, 256 / 128), 256>>>(pacc, pW1, pb1, pt,
                                                            NN, 256, DD, 1);
    gemm_kernel<<<dim3((NN + 127) / 128, DD / 128), 256>>>(pt, pW2, pb2, out,
                                                           NN, DD, 256, 0);
}